// round 17
// baseline (speedup 1.0000x reference)
#include <cuda_runtime.h>
#include <cuda_fp16.h>
#include <cstdint>

// ---------------- problem constants ----------------
#define BATCH 4
#define NHEAD 8
#define NBH   32
#define DH    128
#define TT    2048
#define QT    128
#define KT    64
#define KSPLIT 2
#define THALF (TT / KSPLIT)          // 1024
#define NITER_H (THALF / KT)         // 16
#define SCALE_AL2E 7.21347520444482f // ALPHA * log2(e), folded into Q

__device__ __half g_QT[(size_t)NBH * TT * DH];  // [bh][t][ch], pre-scaled
__device__ __half g_KT[(size_t)NBH * TT * DH];  // [bh][t][ch]
__device__ __half g_VB[(size_t)NBH * DH * TT];  // [bh][dv][t]
__device__ float  g_lsum[(size_t)NBH * TT];     // rowsum accumulator

#define OFF_LS   0
#define OFF_ST   512
#define KBYTES   17408
#define STAGE_BYTES 35840
#define NSTAGE   6
#define SMEM_BYTES (512 + NSTAGE * STAGE_BYTES)
#define LDKB 272
#define LDVB 144
#define LDO  130
#define ONESH2 0x3C003C00u

__device__ __forceinline__ uint32_t smem_u32(const void* p) {
    uint32_t a;
    asm("{ .reg .u64 t; cvta.to.shared.u64 t, %1; cvt.u32.u64 %0, t; }" : "=r"(a) : "l"(p));
    return a;
}
__device__ __forceinline__ void cp16(uint32_t d, const void* g) {
    uint64_t ga;
    asm("cvta.to.global.u64 %0, %1;" : "=l"(ga) : "l"(g));
    asm volatile("cp.async.cg.shared.global [%0], [%1], 16;" :: "r"(d), "l"(ga) : "memory");
}
#define CP_COMMIT() asm volatile("cp.async.commit_group;" ::: "memory")
#define CP_WAIT(n)  asm volatile("cp.async.wait_group %0;" :: "n"(n) : "memory")

__device__ __forceinline__ void ldsm4(uint32_t a, uint32_t* r) {
    asm volatile("ldmatrix.sync.aligned.m8n8.x4.shared.b16 {%0,%1,%2,%3}, [%4];"
        : "=r"(r[0]), "=r"(r[1]), "=r"(r[2]), "=r"(r[3]) : "r"(a));
}
__device__ __forceinline__ void mma16816(float* d, const uint32_t* a, uint32_t b0, uint32_t b1) {
    asm volatile("mma.sync.aligned.m16n8k16.row.col.f32.f16.f16.f32 "
        "{%0,%1,%2,%3}, {%4,%5,%6,%7}, {%8,%9}, {%0,%1,%2,%3};"
        : "+f"(d[0]), "+f"(d[1]), "+f"(d[2]), "+f"(d[3])
        : "r"(a[0]), "r"(a[1]), "r"(a[2]), "r"(a[3]), "r"(b0), "r"(b1));
}
__device__ __forceinline__ uint32_t ex2_f16x2(float lo, float hi) {
    __half2 h = __floats2half2_rn(lo, hi);
    uint32_t x = *reinterpret_cast<uint32_t*>(&h), r;
    asm("ex2.approx.f16x2 %0, %1;" : "=r"(r) : "r"(x));
    return r;
}

__device__ __forceinline__ void cp_ktile(uint32_t dst, const __half* src) {
    const int tid = threadIdx.x;
    #pragma unroll
    for (int j = 0; j < 4; j++) {
        int c = tid + j * 256;
        int row = c >> 4, cc = c & 15;
        cp16(dst + row * LDKB + cc * 16, src + row * DH + cc * 8);
    }
}
__device__ __forceinline__ void cp_vtile(uint32_t dst, const __half* src) {
    const int tid = threadIdx.x;
    #pragma unroll
    for (int j = 0; j < 4; j++) {
        int c = tid + j * 256;
        int row = c >> 3, cc = c & 7;
        cp16(dst + row * LDVB + cc * 16, src + (size_t)row * TT + cc * 8);
    }
}

// ---------------- prep (R13/R14 verified 3-pass) ----------------
__global__ __launch_bounds__(256) void prep_kernel(const float* __restrict__ q,
                                                   const float* __restrict__ k,
                                                   const float* __restrict__ v) {
    __shared__ float part[256];
    __shared__ __align__(16) __half outS[64 * 136];
    const int tid = threadIdx.x;
    const int z = blockIdx.z;

    if (z == 2) {
        const float4* v4 = reinterpret_cast<const float4*>(v);
        uint2* d2 = reinterpret_cast<uint2*>(g_VB);
        const size_t base = ((size_t)(blockIdx.y * gridDim.x + blockIdx.x)) * 2048 + tid;
        #pragma unroll
        for (int j = 0; j < 8; j++) {
            size_t e = base + (size_t)j * 256;
            float4 d = v4[e];
            __half2 h0 = __floats2half2_rn(d.x, d.y);
            __half2 h1 = __floats2half2_rn(d.z, d.w);
            d2[e] = make_uint2(*reinterpret_cast<uint32_t*>(&h0),
                               *reinterpret_cast<uint32_t*>(&h1));
        }
        return;
    }

    const int t = tid & 63, g = tid >> 6;
    const int t0 = blockIdx.x * 64, bh = blockIdx.y;
    const float* src = (z == 0 ? q : k) + (size_t)bh * DH * TT + t0 + t;
    float vals[32];
    #pragma unroll
    for (int i = 0; i < 32; i++) vals[i] = src[(size_t)(g * 32 + i) * TT];

    float ss = 0.f;
    #pragma unroll
    for (int i = 0; i < 32; i++) ss += vals[i] * vals[i];
    part[tid] = ss;
    __syncthreads();
    if (tid < 64)
        part[tid] = 1.0f / fmaxf(sqrtf(part[tid] + part[tid + 64] + part[tid + 128] + part[tid + 192]), 1e-12f);
    __syncthreads();
    const float inv = part[t] * (z == 0 ? SCALE_AL2E : 1.0f);

    #pragma unroll
    for (int i = 0; i < 16; i++) {
        __half2 h = __floats2half2_rn(vals[2 * i] * inv, vals[2 * i + 1] * inv);
        *reinterpret_cast<__half2*>(&outS[t * 136 + g * 32 + 2 * i]) = h;
    }
    __syncthreads();

    uint4* dstg = reinterpret_cast<uint4*>(
        (z == 0 ? g_QT : g_KT) + ((size_t)bh * TT + t0) * DH);
    #pragma unroll
    for (int p = 0; p < 4; p++) {
        int item = tid + p * 256;
        int tt = item >> 4, ch = item & 15;
        dstg[tt * 16 + ch] = *reinterpret_cast<uint4*>(&outS[tt * 136 + ch * 8]);
    }
}

// ---------------- one KT=64 tile (R14 verified compute core) ----------------
__device__ __forceinline__ void compute_tile(uint32_t ks, uint32_t vs,
                                             const uint32_t qA[8][4],
                                             float oacc[16][4], float lacc[4],
                                             uint32_t brow, uint32_t bcol) {
    float sacc[8][4];
    #pragma unroll
    for (int j = 0; j < 8; j++)
        sacc[j][0] = sacc[j][1] = sacc[j][2] = sacc[j][3] = 0.f;

    uint32_t bk[2][4][4];
    #pragma unroll
    for (int j = 0; j < 4; j++)
        ldsm4(ks + (j * 16 + brow) * LDKB + bcol * 2, bk[0][j]);
    #pragma unroll
    for (int c = 0; c < 8; c++) {
        const int cur = c & 1;
        if (c < 7) {
            #pragma unroll
            for (int j = 0; j < 4; j++)
                ldsm4(ks + (j * 16 + brow) * LDKB + ((c + 1) * 16 + bcol) * 2, bk[cur ^ 1][j]);
        }
        #pragma unroll
        for (int j = 0; j < 4; j++) {
            mma16816(sacc[j * 2],     qA[c], bk[cur][j][0], bk[cur][j][1]);
            mma16816(sacc[j * 2 + 1], qA[c], bk[cur][j][2], bk[cur][j][3]);
        }
    }

    uint32_t p[4][4];
    #pragma unroll
    for (int kc = 0; kc < 4; kc++) {
        const float* s0 = sacc[2 * kc];
        const float* s1 = sacc[2 * kc + 1];
        p[kc][0] = ex2_f16x2(s0[0], s0[1]);
        p[kc][1] = ex2_f16x2(s0[2], s0[3]);
        p[kc][2] = ex2_f16x2(s1[0], s1[1]);
        p[kc][3] = ex2_f16x2(s1[2], s1[3]);
    }

    uint32_t bv[2][4][4];
    #pragma unroll
    for (int j = 0; j < 4; j++)
        ldsm4(vs + (j * 16 + brow) * LDVB + bcol * 2, bv[0][j]);
    #pragma unroll
    for (int blk = 0; blk < 8; blk++) {
        const int cur = blk & 1;
        const int kc = blk >> 1, jh = blk & 1;
        if (blk < 7) {
            const int nkc = (blk + 1) >> 1, njh = (blk + 1) & 1;
            #pragma unroll
            for (int j = 0; j < 4; j++)
                ldsm4(vs + ((njh * 4 + j) * 16 + brow) * LDVB + (nkc * 16 + bcol) * 2,
                      bv[cur ^ 1][j]);
        }
        #pragma unroll
        for (int jj = 0; jj < 4; jj++) {
            const int j = jh * 4 + jj;
            mma16816(oacc[j * 2],     p[kc], bv[cur][jj][0], bv[cur][jj][1]);
            mma16816(oacc[j * 2 + 1], p[kc], bv[cur][jj][2], bv[cur][jj][3]);
        }
        if (jh == 1) mma16816(lacc, p[kc], ONESH2, ONESH2);
    }
}

// ---------------- split-K attention: each CTA does half the key range ----------------
__global__ __launch_bounds__(256, 1) void attn_split(float* __restrict__ out) {
    extern __shared__ char smem[];
    const int tid = threadIdx.x;
    const int lane = tid & 31;
    const int wr = tid >> 5;
    const int q0 = blockIdx.x * QT;
    const int bh = blockIdx.y;
    const int kh = blockIdx.z;              // key half 0/1
    const uint32_t sb = smem_u32(smem);

    const __half* gq = g_QT + ((size_t)bh * TT + q0) * DH;
    const __half* gk = g_KT + ((size_t)bh * TT + (size_t)kh * THALF) * DH;
    const __half* gv = g_VB + (size_t)bh * DH * TT + (size_t)kh * THALF;

    // ---- stage Q tile into stage0, extract persistent A-frags ----
    #pragma unroll
    for (int j = 0; j < 8; j++) {
        int c = tid + j * 256;
        int row = c >> 4, cc = c & 15;
        cp16(sb + OFF_ST + row * LDKB + cc * 16, gq + row * DH + cc * 8);
    }
    CP_COMMIT();
    CP_WAIT(0);
    __syncthreads();

    uint32_t qA[8][4];
    {
        const uint32_t arow = ((lane >> 3) & 1) * 8 + (lane & 7);
        const uint32_t acol = ((lane >> 4) & 1) * 8;
        const uint32_t qb = sb + OFF_ST + (wr * 16 + arow) * LDKB + acol * 2;
        #pragma unroll
        for (int c = 0; c < 8; c++) ldsm4(qb + c * 32, qA[c]);
    }
    __syncthreads();

    // ---- prefetch tile groups {0,1} and {2,3} ----
    #pragma unroll
    for (int g2 = 0; g2 < 2; g2++) {
        #pragma unroll
        for (int s = 0; s < 2; s++) {
            const int t = g2 * 2 + s;
            cp_ktile(sb + OFF_ST + t * STAGE_BYTES, gk + (size_t)t * KT * DH);
            cp_vtile(sb + OFF_ST + t * STAGE_BYTES + KBYTES, gv + t * KT);
        }
        CP_COMMIT();
    }

    float oacc[16][4];
    #pragma unroll
    for (int j = 0; j < 16; j++)
        oacc[j][0] = oacc[j][1] = oacc[j][2] = oacc[j][3] = 0.f;
    float lacc[4] = {0.f, 0.f, 0.f, 0.f};

    const uint32_t brow = ((lane >> 4) & 1) * 8 + (lane & 7);
    const uint32_t bcol = ((lane >> 3) & 1) * 8;

    for (int ii = 0; ii < NITER_H; ii += 2) {
        if (ii < NITER_H - 2) { CP_WAIT(1); } else { CP_WAIT(0); }
        __syncthreads();

        if (ii + 4 < NITER_H) {
            #pragma unroll
            for (int s = 0; s < 2; s++) {
                const int t = ii + 4 + s;
                const uint32_t st = sb + OFF_ST + (t % NSTAGE) * STAGE_BYTES;
                cp_ktile(st, gk + (size_t)t * KT * DH);
                cp_vtile(st + KBYTES, gv + (size_t)t * KT);
            }
            CP_COMMIT();
        }

        const uint32_t s0 = sb + OFF_ST + (ii % NSTAGE) * STAGE_BYTES;
        compute_tile(s0, s0 + KBYTES, qA, oacc, lacc, brow, bcol);
        const uint32_t s1 = sb + OFF_ST + ((ii + 1) % NSTAGE) * STAGE_BYTES;
        compute_tile(s1, s1 + KBYTES, qA, oacc, lacc, brow, bcol);
    }

    // ---- epilogue: stage O, atomically accumulate partials ----
    __syncthreads();
    float* Osf = reinterpret_cast<float*>(smem + OFF_ST);
    const int r2 = lane >> 2, tg = lane & 3;
    #pragma unroll
    for (int jj = 0; jj < 16; jj++) {
        float2 v01 = make_float2(oacc[jj][0], oacc[jj][1]);
        float2 v23 = make_float2(oacc[jj][2], oacc[jj][3]);
        *reinterpret_cast<float2*>(&Osf[(wr * 16 + r2) * LDO + jj * 8 + tg * 2]) = v01;
        *reinterpret_cast<float2*>(&Osf[(wr * 16 + r2 + 8) * LDO + jj * 8 + tg * 2]) = v23;
    }
    if (tg == 0) {
        atomicAdd(&g_lsum[(size_t)bh * TT + q0 + wr * 16 + r2],     lacc[0]);
        atomicAdd(&g_lsum[(size_t)bh * TT + q0 + wr * 16 + r2 + 8], lacc[2]);
    }
    __syncthreads();

    float* ob = out + (size_t)bh * DH * TT + q0;
    #pragma unroll
    for (int dvi = 0; dvi < 16; dvi++) {
        const int dv = wr * 16 + dvi;
        #pragma unroll
        for (int s = 0; s < 4; s++) {
            const int qq = lane + s * 32;
            atomicAdd(&ob[(size_t)dv * TT + qq], Osf[qq * LDO + dv]);
        }
    }
}

// ---------------- normalize: out[bh][dv][t] /= lsum[bh][t] ----------------
__global__ __launch_bounds__(128) void norm_kernel(float* __restrict__ out) {
    const int tid = threadIdx.x;
    const int tch = blockIdx.x;             // 0..3 (512 t each)
    const int bh = blockIdx.y;
    const int t4 = tch * 128 + tid;         // float4 index along t

    float4 ls = *reinterpret_cast<const float4*>(&g_lsum[(size_t)bh * TT + t4 * 4]);
    float4 inv = make_float4(1.0f / ls.x, 1.0f / ls.y, 1.0f / ls.z, 1.0f / ls.w);

    float4* o = reinterpret_cast<float4*>(out + (size_t)bh * DH * TT);
    #pragma unroll 4
    for (int dv = 0; dv < DH; dv++) {
        float4 vv = o[dv * (TT / 4) + t4];
        vv.x *= inv.x; vv.y *= inv.y; vv.z *= inv.z; vv.w *= inv.w;
        o[dv * (TT / 4) + t4] = vv;
    }
}

extern "C" void kernel_launch(void* const* d_in, const int* in_sizes, int n_in,
                              void* d_out, int out_size) {
    const float* q = (const float*)d_in[0];
    const float* k = (const float*)d_in[1];
    const float* v = (const float*)d_in[2];
    float* out = (float*)d_out;

    cudaFuncSetAttribute(attn_split, cudaFuncAttributeMaxDynamicSharedMemorySize, SMEM_BYTES);

    void* lsum_ptr = nullptr;
    cudaGetSymbolAddress(&lsum_ptr, g_lsum);
    cudaMemsetAsync(lsum_ptr, 0, (size_t)NBH * TT * sizeof(float));
    cudaMemsetAsync(out, 0, (size_t)out_size * sizeof(float));

    prep_kernel<<<dim3(TT / 64, NBH, 3), 256>>>(q, k, v);
    attn_split<<<dim3(TT / QT, NBH, KSPLIT), 256, SMEM_BYTES>>>(out);
    norm_kernel<<<dim3(4, NBH), 128>>>(out);
}